// round 3
// baseline (speedup 1.0000x reference)
#include <cuda_runtime.h>
#include <math.h>

#define BB 16
#define NN (1 << 20)
#define HB 65536
#define HARD 512
#define RANDN 512
#define ULEN (NN - HARD)        // 1048064 (divisible by 4)
#define UCAP 8192
#define MAXSLOTS 1152
#define SLOTCAP 96
#define PARTS 8
#define CHUNK (NN / PARTS)      // 131072
#define HWORDS (HB / 2)         // 32768 packed u16x2 words

// ---------------- scratch (static __device__, no allocs) ----------------
__device__ unsigned int g_hist_parts[BB * PARTS * HWORDS];  // 16MB, fully overwritten each run
__device__ unsigned int g_S[BB * (HB + 1)];
__device__ unsigned int g_num_pos[BB];
__device__ float        g_pos_loss[BB];
__device__ unsigned int g_pos_bits[BB * (NN / 32)];
__device__ int          g_M[BB];
__device__ unsigned int g_numneg[BB];
__device__ unsigned int g_ucand_cnt[BB];
__device__ float2       g_ucand[BB * UCAP];
__device__ unsigned int g_ranks[BB * RANDN];
__device__ unsigned int g_nranks[BB];
__device__ int          g_slot[BB * HB];          // -1 none, -2 marked, >=0 slot id
__device__ unsigned int g_bmask[BB * (HB / 32)];  // bucket-needed bitmask (8KB/image)
__device__ unsigned int g_nslots[BB];
__device__ unsigned int g_slot_cnt[BB * MAXSLOTS];
__device__ float        g_slot_vals[BB * MAXSLOTS * SLOTCAP];

__device__ __forceinline__ int conf_bucket(float c) {
    int b = (int)(c * 65536.0f);
    b = b < 0 ? 0 : (b > HB - 1 ? HB - 1 : b);
    return b;
}

__device__ __forceinline__ int find_bucket(const unsigned int* S, unsigned int q) {
    int lo = 0, hi = HB;
    while (hi - lo > 1) {
        int mid = (lo + hi) >> 1;
        if (S[mid] > q) lo = mid; else hi = mid;
    }
    return lo;
}

// ---------------- K1: init ----------------
__global__ void k_init() {
    int idx = blockIdx.x * blockDim.x + threadIdx.x;
    int stride = gridDim.x * blockDim.x;
    for (int i = idx; i < BB * HB; i += stride) g_slot[i] = -1;
    for (int i = idx; i < BB * (HB / 32); i += stride) g_bmask[i] = 0u;
    for (int i = idx; i < BB * MAXSLOTS; i += stride) g_slot_cnt[i] = 0u;
    if (idx < BB) {
        g_num_pos[idx] = 0u; g_pos_loss[idx] = 0.0f;
        g_ucand_cnt[idx] = 0u; g_nranks[idx] = 0u; g_nslots[idx] = 0u;
    }
}

// ---------------- K2: main pass, SMEM-privatized 16-bit histogram ----------------
__global__ void k_pass1(const unsigned int* __restrict__ pos, const float* __restrict__ conf) {
    extern __shared__ unsigned int sh[];          // HWORDS words = 128KB
    int bid = blockIdx.x;                          // 128 blocks: img*8 + part
    int img = bid >> 3;
    int part = bid & 7;
    int t = threadIdx.x;                           // 1024 threads

    for (int i = t; i < HWORDS; i += 1024) sh[i] = 0u;
    __syncthreads();

    int base = img * NN + part * CHUNK;
    float pl = 0.0f;
    int pc = 0;
    #pragma unroll 4
    for (int k = 0; k < CHUNK / 1024; k++) {       // 128 iterations
        int idx = base + k * 1024 + t;
        unsigned int p = pos[idx];
        float c = conf[idx];
        unsigned int ball = __ballot_sync(0xffffffffu, p != 0u);
        if ((t & 31) == 0) g_pos_bits[idx >> 5] = ball;
        if (p != 0u) {
            pl += -fmaxf(logf(c), -100.0f);
            pc++;
        } else {
            int b = conf_bucket(c);
            atomicAdd(&sh[b >> 1], 1u << ((b & 1) * 16));
        }
    }
    __syncthreads();

    unsigned int* dst = &g_hist_parts[(unsigned int)bid * HWORDS];
    for (int i = t; i < HWORDS; i += 1024) dst[i] = sh[i];
    __syncthreads();

    // block reduce pos stats (reuse smem)
    for (int o = 16; o; o >>= 1) {
        pl += __shfl_down_sync(0xffffffffu, pl, o);
        pc += __shfl_down_sync(0xffffffffu, pc, o);
    }
    float* s_pl = (float*)sh;
    int* s_pc = (int*)(sh + 64);
    int w = t >> 5;
    if ((t & 31) == 0) { s_pl[w] = pl; s_pc[w] = pc; }
    __syncthreads();
    if (t == 0) {
        float tp = 0.0f; int tc = 0;
        for (int i = 0; i < 32; i++) { tp += s_pl[i]; tc += s_pc[i]; }
        atomicAdd(&g_pos_loss[img], tp);
        atomicAdd(&g_num_pos[img], (unsigned int)tc);
    }
}

// ---------------- K3: sum parts + suffix CDF per image ----------------
__global__ void k_scan() {
    int img = blockIdx.x;
    int t = threadIdx.x;                           // 256 threads
    const unsigned int* parts = &g_hist_parts[(unsigned int)img * PARTS * HWORDS];
    unsigned int* S = &g_S[img * (HB + 1)];
    __shared__ unsigned int chunk[256];
    __shared__ unsigned int suf[257];

    unsigned int s = 0;
    for (int p = 0; p < PARTS; p++) {
        const unsigned int* hp = parts + p * HWORDS + t * 128;
        for (int i = 0; i < 128; i++) { unsigned int w = hp[i]; s += (w & 0xffffu) + (w >> 16); }
    }
    chunk[t] = s;
    __syncthreads();
    if (t == 0) {
        suf[256] = 0;
        for (int i = 255; i >= 0; i--) suf[i] = suf[i + 1] + chunk[i];
    }
    __syncthreads();
    unsigned int run = suf[t + 1];
    for (int i = 255; i >= 0; i--) {
        int b = t * 256 + i;
        unsigned int cnt = 0;
        for (int p = 0; p < PARTS; p++) {
            unsigned int w = parts[p * HWORDS + (b >> 1)];
            cnt += (w >> ((b & 1) * 16)) & 0xffffu;
        }
        run += cnt;
        S[b] = run;
    }
    if (t == 0) {
        S[HB] = 0;
        g_numneg[img] = suf[0];
        g_M[img] = (int)suf[0] - HARD;
    }
}

// ---------------- K4: filter small u among i < M (2D grid, float4) ----------------
__global__ void k_ufilter(const float* __restrict__ u) {
    int img = blockIdx.y;
    int i4 = blockIdx.x * 256 + threadIdx.x;       // grid.x = 1024 -> 262144 > ULEN/4
    if (i4 >= ULEN / 4) return;
    int M = g_M[img];
    float th = (M <= 4096) ? 2.0f : (1280.0f / (float)M);
    float4 v = *(const float4*)(u + (size_t)img * ULEN + (size_t)i4 * 4);
    int i0 = i4 * 4;
    #pragma unroll
    for (int j = 0; j < 4; j++) {
        float uv = (j == 0) ? v.x : (j == 1) ? v.y : (j == 2) ? v.z : v.w;
        int i = i0 + j;
        if (i < M && uv < th) {
            unsigned int p = atomicAdd(&g_ucand_cnt[img], 1u);
            if (p < UCAP) g_ucand[img * UCAP + p] = make_float2(uv, __int_as_float(i));
        }
    }
}

// ---------------- K5: exact 512-smallest (u, idx) selection ----------------
__global__ void k_select() {
    int img = blockIdx.x >> 5;
    int t = (blockIdx.x & 31) * 256 + threadIdx.x;
    unsigned int cnt = g_ucand_cnt[img];
    if (cnt > UCAP) cnt = UCAP;
    if ((unsigned int)t >= cnt) return;
    const float2* base = &g_ucand[img * UCAP];
    float2 me = base[t];
    float mu = me.x; int mi = __float_as_int(me.y);
    int r = 0;
    for (unsigned int j = 0; j < cnt; j++) {
        float2 o = base[j];
        int oi = __float_as_int(o.y);
        r += (o.x < mu) || (o.x == mu && oi < mi);
    }
    if (r < RANDN) {
        unsigned int p = atomicAdd(&g_nranks[img], 1u);
        g_ranks[img * RANDN + p] = (unsigned int)(HARD + mi);
    }
}

// ---------------- K6a: mark needed buckets (+ bitmask) ----------------
__global__ void k_mark() {
    int img = blockIdx.x;
    const unsigned int* S = &g_S[img * (HB + 1)];
    unsigned int nn = g_numneg[img];
    int HC = nn < HARD ? (int)nn : HARD;
    int nr = (int)g_nranks[img];
    int total = HC + nr;
    for (int qi = threadIdx.x; qi < total; qi += blockDim.x) {
        unsigned int q = (qi < HC) ? (unsigned int)qi : g_ranks[img * RANDN + (qi - HC)];
        int b = find_bucket(S, q);
        g_slot[img * HB + b] = -2;
        atomicOr(&g_bmask[img * (HB / 32) + (b >> 5)], 1u << (b & 31));
    }
}

// ---------------- K6b: compact slot ids ----------------
__global__ void k_compact() {
    int idx = blockIdx.x * 256 + threadIdx.x;      // covers BB*HB exactly
    int img = idx >> 16;
    if (g_slot[idx] == -2) g_slot[idx] = (int)atomicAdd(&g_nslots[img], 1u);
}

// ---------------- K8: collect, SMEM bitmask filter ----------------
__global__ void k_collect(const float* __restrict__ conf) {
    __shared__ unsigned int mask[HB / 32];          // 8KB
    int img = blockIdx.y;
    for (int i = threadIdx.x; i < HB / 32; i += 256) mask[i] = g_bmask[img * (HB / 32) + i];
    __syncthreads();

    int tix = blockIdx.x * 256 + threadIdx.x;       // grid.x = 512 -> 131072 threads
    int base = img * NN;
    #pragma unroll
    for (int k = 0; k < 8; k++) {
        int idx = base + k * 131072 + tix;
        unsigned int bits = g_pos_bits[idx >> 5];
        float c = conf[idx];
        if ((bits >> (idx & 31)) & 1u) continue;    // positive -> skip
        int b = conf_bucket(c);
        if ((mask[b >> 5] >> (b & 31)) & 1u) {
            int s = g_slot[img * HB + b];
            unsigned int p = atomicAdd(&g_slot_cnt[img * MAXSLOTS + s], 1u);
            if (p < SLOTCAP) g_slot_vals[(img * MAXSLOTS + s) * SLOTCAP + p] = c;
        }
    }
}

// ---------------- K9: rank queries + final reduction ----------------
__global__ void k_final(float* __restrict__ out) {
    int img = blockIdx.x;
    const unsigned int* S = &g_S[img * (HB + 1)];
    unsigned int nn = g_numneg[img];
    int HC = nn < HARD ? (int)nn : HARD;
    int nr = (int)g_nranks[img];
    int total = HC + nr;
    float hard = 0.0f, rnd = 0.0f;
    for (int qi = threadIdx.x; qi < total; qi += blockDim.x) {
        bool isHard = qi < HC;
        unsigned int q = isHard ? (unsigned int)qi : g_ranks[img * RANDN + (qi - HC)];
        int b = find_bucket(S, q);
        unsigned int j = q - S[b + 1];
        int s = g_slot[img * HB + b];
        unsigned int c = g_slot_cnt[img * MAXSLOTS + s];
        if (c > SLOTCAP) c = SLOTCAP;
        const float* V = &g_slot_vals[(img * MAXSLOTS + s) * SLOTCAP];
        float v = 0.5f;
        for (unsigned int k = 0; k < c; k++) {
            float x = V[k];
            unsigned int g = 0, e = 0;
            for (unsigned int l = 0; l < c; l++) { float y = V[l]; g += (y > x); e += (y == x); }
            if (g <= j && j < g + e) { v = x; break; }
        }
        float term = -fmaxf(logf(1.0f - v), -100.0f);
        if (isHard) hard += term; else rnd += term;
    }
    for (int o = 16; o; o >>= 1) {
        hard += __shfl_down_sync(0xffffffffu, hard, o);
        rnd  += __shfl_down_sync(0xffffffffu, rnd, o);
    }
    __shared__ float sh2[8], sr2[8];
    int w = threadIdx.x >> 5;
    if ((threadIdx.x & 31) == 0) { sh2[w] = hard; sr2[w] = rnd; }
    __syncthreads();
    if (threadIdx.x == 0) {
        float H = 0.0f, R = 0.0f;
        for (int i = 0; i < 8; i++) { H += sh2[i]; R += sr2[i]; }
        float P = g_pos_loss[img];
        float outv;
        if (g_M[img] > 0) {
            outv = P + H + R;
        } else {
            float sn = (float)(g_num_pos[img] + (unsigned int)HC);
            outv = (P + H) / fmaxf(sn, 1.0f);
        }
        out[img] = outv;
    }
}

extern "C" void kernel_launch(void* const* d_in, const int* in_sizes, int n_in,
                              void* d_out, int out_size) {
    const unsigned int* pos = (const unsigned int*)d_in[0];
    const float* conf = (const float*)d_in[1];
    const float* u = (const float*)d_in[2];
    float* out = (float*)d_out;
    (void)in_sizes; (void)n_in; (void)out_size;

    cudaFuncSetAttribute(k_pass1, cudaFuncAttributeMaxDynamicSharedMemorySize, HWORDS * 4);

    k_init<<<2048, 256>>>();
    k_pass1<<<BB * PARTS, 1024, HWORDS * 4>>>(pos, conf);
    k_scan<<<BB, 256>>>();
    {
        dim3 g(1024, BB);
        k_ufilter<<<g, 256>>>(u);
    }
    k_select<<<BB * 32, 256>>>();
    k_mark<<<BB, 256>>>();
    k_compact<<<BB * HB / 256, 256>>>();
    {
        dim3 g(512, BB);
        k_collect<<<g, 256>>>(conf);
    }
    k_final<<<BB, 256>>>(out);
}

// round 4
// speedup vs baseline: 1.8044x; 1.8044x over previous
#include <cuda_runtime.h>
#include <math.h>

#define BB 16
#define NN (1 << 20)
#define HB 65536
#define HWRD (HB / 32)          // 2048 bitmask words per image
#define HARD 512
#define RANDN 512
#define ULEN (NN - HARD)        // 1048064 (divisible by 4)
#define UCAP 8192
#define MAXSLOTS 1152
#define SLOTCAP 96

// ---------------- scratch (static __device__, no allocs) ----------------
__device__ unsigned int g_hist[BB * HB];          // 4MB
__device__ unsigned int g_S[BB * (HB + 1)];       // suffix CDF
__device__ unsigned int g_num_pos[BB];
__device__ float        g_pos_loss[BB];
__device__ int          g_M[BB];
__device__ unsigned int g_numneg[BB];
__device__ unsigned int g_ucand_cnt[BB];
__device__ float2       g_ucand[BB * UCAP];
__device__ unsigned int g_ranks[BB * RANDN];
__device__ unsigned int g_nranks[BB];
__device__ unsigned int g_bmask[BB * HWRD];       // needed-bucket bitmask
__device__ unsigned int g_wpref[BB * HWRD];       // exclusive prefix popcount of bmask
__device__ unsigned int g_slot_cnt[BB * MAXSLOTS];
__device__ float        g_slot_vals[BB * MAXSLOTS * SLOTCAP];

__device__ __forceinline__ int conf_bucket(float c) {
    int b = (int)(c * 65536.0f);
    b = b < 0 ? 0 : (b > HB - 1 ? HB - 1 : b);
    return b;
}

__device__ __forceinline__ int find_bucket(const unsigned int* S, unsigned int q) {
    int lo = 0, hi = HB;
    while (hi - lo > 1) {
        int mid = (lo + hi) >> 1;
        if (S[mid] > q) lo = mid; else hi = mid;
    }
    return lo;
}

// ---------------- K1: init ----------------
__global__ void k_init() {
    int idx = blockIdx.x * blockDim.x + threadIdx.x;
    int stride = gridDim.x * blockDim.x;
    for (int i = idx; i < BB * HB; i += stride) g_hist[i] = 0u;
    for (int i = idx; i < BB * HWRD; i += stride) g_bmask[i] = 0u;
    for (int i = idx; i < BB * MAXSLOTS; i += stride) g_slot_cnt[i] = 0u;
    if (idx < BB) {
        g_num_pos[idx] = 0u; g_pos_loss[idx] = 0.0f;
        g_ucand_cnt[idx] = 0u; g_nranks[idx] = 0u;
    }
}

// ---------------- K2: histogram + pos stats (global REDs) ----------------
__global__ void k_pass1(const uint4* __restrict__ pos, const float4* __restrict__ conf) {
    int img = blockIdx.y;
    int i4 = blockIdx.x * 256 + threadIdx.x;        // 0..262143, grid.x = 1024
    size_t b4 = (size_t)img * (NN / 4) + i4;
    uint4 p = pos[b4];
    float4 c = conf[b4];
    unsigned int* h = &g_hist[img * HB];

    float pl = 0.0f; int pc = 0;
    if (p.x) { pl += -fmaxf(logf(c.x), -100.0f); pc++; } else atomicAdd(&h[conf_bucket(c.x)], 1u);
    if (p.y) { pl += -fmaxf(logf(c.y), -100.0f); pc++; } else atomicAdd(&h[conf_bucket(c.y)], 1u);
    if (p.z) { pl += -fmaxf(logf(c.z), -100.0f); pc++; } else atomicAdd(&h[conf_bucket(c.z)], 1u);
    if (p.w) { pl += -fmaxf(logf(c.w), -100.0f); pc++; } else atomicAdd(&h[conf_bucket(c.w)], 1u);

    for (int o = 16; o; o >>= 1) {
        pl += __shfl_down_sync(0xffffffffu, pl, o);
        pc += __shfl_down_sync(0xffffffffu, pc, o);
    }
    __shared__ float s_pl[8]; __shared__ int s_pc[8];
    int w = threadIdx.x >> 5;
    if ((threadIdx.x & 31) == 0) { s_pl[w] = pl; s_pc[w] = pc; }
    __syncthreads();
    if (threadIdx.x == 0) {
        float tp = 0.0f; int tc = 0;
        #pragma unroll
        for (int i = 0; i < 8; i++) { tp += s_pl[i]; tc += s_pc[i]; }
        atomicAdd(&g_pos_loss[img], tp);
        atomicAdd(&g_num_pos[img], (unsigned int)tc);
    }
}

// ---------------- K3: suffix CDF per image (1024 threads, 64 bins each) ----------------
__global__ void k_scan() {
    int img = blockIdx.x;
    int t = threadIdx.x;                             // 1024
    const unsigned int* h = &g_hist[img * HB];
    unsigned int* S = &g_S[img * (HB + 1)];
    __shared__ unsigned int ps[1024];

    unsigned int s = 0;
    #pragma unroll 8
    for (int i = 0; i < 64; i++) s += h[t * 64 + i];
    ps[t] = s;
    __syncthreads();
    // inclusive suffix scan (Hillis-Steele)
    for (int off = 1; off < 1024; off <<= 1) {
        unsigned int v = (t + off < 1024) ? ps[t + off] : 0u;
        __syncthreads();
        ps[t] += v;
        __syncthreads();
    }
    unsigned int run = (t < 1023) ? ps[t + 1] : 0u;
    for (int i = 63; i >= 0; i--) {
        int b = t * 64 + i;
        run += h[b];
        S[b] = run;
    }
    if (t == 0) {
        S[HB] = 0;
        g_numneg[img] = ps[0];
        g_M[img] = (int)ps[0] - HARD;
    }
}

// ---------------- K4: filter small u among i < M ----------------
__global__ void k_ufilter(const float* __restrict__ u) {
    int img = blockIdx.y;
    int i4 = blockIdx.x * 256 + threadIdx.x;
    if (i4 >= ULEN / 4) return;
    int M = g_M[img];
    float th = (M <= 4096) ? 2.0f : (1280.0f / (float)M);
    float4 v = *(const float4*)(u + (size_t)img * ULEN + (size_t)i4 * 4);
    int i0 = i4 * 4;
    #pragma unroll
    for (int j = 0; j < 4; j++) {
        float uv = (j == 0) ? v.x : (j == 1) ? v.y : (j == 2) ? v.z : v.w;
        int i = i0 + j;
        if (i < M && uv < th) {
            unsigned int p = atomicAdd(&g_ucand_cnt[img], 1u);
            if (p < UCAP) g_ucand[img * UCAP + p] = make_float2(uv, __int_as_float(i));
        }
    }
}

// ---------------- K5: exact 512-smallest (u, idx) ----------------
__global__ void k_select() {
    int img = blockIdx.x >> 5;
    int t = (blockIdx.x & 31) * 256 + threadIdx.x;
    unsigned int cnt = g_ucand_cnt[img];
    if (cnt > UCAP) cnt = UCAP;
    if ((unsigned int)t >= cnt) return;
    const float2* base = &g_ucand[img * UCAP];
    float2 me = base[t];
    float mu = me.x; int mi = __float_as_int(me.y);
    int r = 0;
    for (unsigned int j = 0; j < cnt; j++) {
        float2 o = base[j];
        int oi = __float_as_int(o.y);
        r += (o.x < mu) || (o.x == mu && oi < mi);
    }
    if (r < RANDN) {
        unsigned int p = atomicAdd(&g_nranks[img], 1u);
        g_ranks[img * RANDN + p] = (unsigned int)(HARD + mi);
    }
}

// ---------------- K6: mark needed buckets (bitmask only) ----------------
__global__ void k_mark() {
    int img = blockIdx.x;
    const unsigned int* S = &g_S[img * (HB + 1)];
    unsigned int nn = g_numneg[img];
    int HC = nn < HARD ? (int)nn : HARD;
    int nr = (int)g_nranks[img];
    int total = HC + nr;
    for (int qi = threadIdx.x; qi < total; qi += blockDim.x) {
        unsigned int q = (qi < HC) ? (unsigned int)qi : g_ranks[img * RANDN + (qi - HC)];
        int b = find_bucket(S, q);
        atomicOr(&g_bmask[img * HWRD + (b >> 5)], 1u << (b & 31));
    }
}

// ---------------- K7: exclusive prefix popcount of bitmask ----------------
__global__ void k_wpref() {
    int img = blockIdx.x;
    int t = threadIdx.x;                             // 256, 8 words each
    const unsigned int* bm = &g_bmask[img * HWRD];
    unsigned int* wp = &g_wpref[img * HWRD];
    __shared__ unsigned int ps[256];
    unsigned int loc[8];
    unsigned int s = 0;
    #pragma unroll
    for (int i = 0; i < 8; i++) { loc[i] = __popc(bm[t * 8 + i]); s += loc[i]; }
    ps[t] = s;
    __syncthreads();
    for (int off = 1; off < 256; off <<= 1) {
        unsigned int v = (t >= off) ? ps[t - off] : 0u;
        __syncthreads();
        ps[t] += v;
        __syncthreads();
    }
    unsigned int run = (t > 0) ? ps[t - 1] : 0u;     // exclusive prefix of my chunk
    #pragma unroll
    for (int i = 0; i < 8; i++) { wp[t * 8 + i] = run; run += loc[i]; }
}

// ---------------- K8: collect elements of needed buckets ----------------
__global__ void k_collect(const float4* __restrict__ conf, const unsigned int* __restrict__ pos) {
    __shared__ unsigned int mask[HWRD];
    __shared__ unsigned int wpref[HWRD];
    int img = blockIdx.y;
    for (int i = threadIdx.x; i < HWRD; i += 256) {
        mask[i] = g_bmask[img * HWRD + i];
        wpref[i] = g_wpref[img * HWRD + i];
    }
    __syncthreads();

    int i4 = blockIdx.x * 256 + threadIdx.x;         // grid.x = 1024
    size_t b4 = (size_t)img * (NN / 4) + i4;
    float4 c = conf[b4];
    int base_idx = i4 * 4;
    #pragma unroll
    for (int j = 0; j < 4; j++) {
        float cv = (j == 0) ? c.x : (j == 1) ? c.y : (j == 2) ? c.z : c.w;
        int b = conf_bucket(cv);
        unsigned int mw = mask[b >> 5];
        if ((mw >> (b & 31)) & 1u) {
            // lazy positivity check (rare path)
            if (pos[(size_t)img * NN + base_idx + j] != 0u) continue;
            int s = (int)(wpref[b >> 5] + __popc(mw & ((1u << (b & 31)) - 1u)));
            unsigned int p = atomicAdd(&g_slot_cnt[img * MAXSLOTS + s], 1u);
            if (p < SLOTCAP) g_slot_vals[(img * MAXSLOTS + s) * SLOTCAP + p] = cv;
        }
    }
}

// ---------------- K9: rank queries + final reduction ----------------
__global__ void k_final(float* __restrict__ out) {
    int img = blockIdx.x;
    const unsigned int* S = &g_S[img * (HB + 1)];
    const unsigned int* bm = &g_bmask[img * HWRD];
    const unsigned int* wp = &g_wpref[img * HWRD];
    unsigned int nn = g_numneg[img];
    int HC = nn < HARD ? (int)nn : HARD;
    int nr = (int)g_nranks[img];
    int total = HC + nr;
    float hard = 0.0f, rnd = 0.0f;
    for (int qi = threadIdx.x; qi < total; qi += blockDim.x) {
        bool isHard = qi < HC;
        unsigned int q = isHard ? (unsigned int)qi : g_ranks[img * RANDN + (qi - HC)];
        int b = find_bucket(S, q);
        unsigned int j = q - S[b + 1];
        unsigned int mw = bm[b >> 5];
        int s = (int)(wp[b >> 5] + __popc(mw & ((1u << (b & 31)) - 1u)));
        unsigned int c = g_slot_cnt[img * MAXSLOTS + s];
        if (c > SLOTCAP) c = SLOTCAP;
        const float* V = &g_slot_vals[(img * MAXSLOTS + s) * SLOTCAP];
        float v = 0.5f;
        for (unsigned int k = 0; k < c; k++) {
            float x = V[k];
            unsigned int g = 0, e = 0;
            for (unsigned int l = 0; l < c; l++) { float y = V[l]; g += (y > x); e += (y == x); }
            if (g <= j && j < g + e) { v = x; break; }
        }
        float term = -fmaxf(logf(1.0f - v), -100.0f);
        if (isHard) hard += term; else rnd += term;
    }
    for (int o = 16; o; o >>= 1) {
        hard += __shfl_down_sync(0xffffffffu, hard, o);
        rnd  += __shfl_down_sync(0xffffffffu, rnd, o);
    }
    __shared__ float sh2[8], sr2[8];
    int w = threadIdx.x >> 5;
    if ((threadIdx.x & 31) == 0) { sh2[w] = hard; sr2[w] = rnd; }
    __syncthreads();
    if (threadIdx.x == 0) {
        float H = 0.0f, R = 0.0f;
        for (int i = 0; i < 8; i++) { H += sh2[i]; R += sr2[i]; }
        float P = g_pos_loss[img];
        float outv;
        if (g_M[img] > 0) {
            outv = P + H + R;
        } else {
            float sn = (float)(g_num_pos[img] + (unsigned int)HC);
            outv = (P + H) / fmaxf(sn, 1.0f);
        }
        out[img] = outv;
    }
}

extern "C" void kernel_launch(void* const* d_in, const int* in_sizes, int n_in,
                              void* d_out, int out_size) {
    const unsigned int* pos = (const unsigned int*)d_in[0];
    const float* conf = (const float*)d_in[1];
    const float* u = (const float*)d_in[2];
    float* out = (float*)d_out;
    (void)in_sizes; (void)n_in; (void)out_size;

    k_init<<<2048, 256>>>();
    {
        dim3 g(1024, BB);
        k_pass1<<<g, 256>>>((const uint4*)pos, (const float4*)conf);
    }
    k_scan<<<BB, 1024>>>();
    {
        dim3 g(1024, BB);
        k_ufilter<<<g, 256>>>(u);
    }
    k_select<<<BB * 32, 256>>>();
    k_mark<<<BB, 256>>>();
    k_wpref<<<BB, 256>>>();
    {
        dim3 g(1024, BB);
        k_collect<<<g, 256>>>((const float4*)conf, pos);
    }
    k_final<<<BB, 256>>>(out);
}

// round 5
// speedup vs baseline: 1.8883x; 1.0465x over previous
#include <cuda_runtime.h>
#include <math.h>

#define BB 16
#define NN (1 << 20)
#define HB 65536
#define HWRD (HB / 32)          // 2048 bitmask words per image
#define HARD 512
#define RANDN 512
#define ULEN (NN - HARD)        // 1048064 (divisible by 4)
#define U4 (ULEN / 4)           // 262016
#define UCAP 16384
#define MAXSLOTS 1152
#define SLOTCAP 96
#define TH0 1.5e-3f
#define TRIG_M 853334           // fallback refilter when M < 1280/TH0

// ---------------- scratch (static __device__, no allocs) ----------------
__device__ unsigned int g_hist[BB * HB];          // 4MB
__device__ unsigned int g_S[BB * (HB + 1)];       // suffix CDF
__device__ unsigned int g_num_pos[BB];
__device__ float        g_pos_loss[BB];
__device__ int          g_M[BB];
__device__ unsigned int g_numneg[BB];
__device__ unsigned int g_ucand_cnt[BB];
__device__ float2       g_ucand[BB * UCAP];
__device__ unsigned int g_ranks[BB * RANDN];
__device__ unsigned int g_nranks[BB];
__device__ unsigned int g_bmask[BB * HWRD];       // needed-bucket bitmask
__device__ unsigned int g_wpref[BB * HWRD];       // exclusive prefix popcount
__device__ unsigned int g_slot_cnt[BB * MAXSLOTS];
__device__ float        g_slot_vals[BB * MAXSLOTS * SLOTCAP];

__device__ __forceinline__ int conf_bucket(float c) {
    int b = (int)(c * 65536.0f);
    b = b < 0 ? 0 : (b > HB - 1 ? HB - 1 : b);
    return b;
}

__device__ __forceinline__ int find_bucket(const unsigned int* S, unsigned int q) {
    int lo = 0, hi = HB;
    while (hi - lo > 1) {
        int mid = (lo + hi) >> 1;
        if (S[mid] > q) lo = mid; else hi = mid;
    }
    return lo;
}

// ---------------- K1: init ----------------
__global__ void k_init() {
    int idx = blockIdx.x * blockDim.x + threadIdx.x;
    int stride = gridDim.x * blockDim.x;
    for (int i = idx; i < BB * HB; i += stride) g_hist[i] = 0u;
    for (int i = idx; i < BB * HWRD; i += stride) g_bmask[i] = 0u;
    for (int i = idx; i < BB * MAXSLOTS; i += stride) g_slot_cnt[i] = 0u;
    if (idx < BB) {
        g_num_pos[idx] = 0u; g_pos_loss[idx] = 0.0f;
        g_ucand_cnt[idx] = 0u; g_nranks[idx] = 0u;
    }
}

// ---------------- K2: fused histogram + pos stats + u prefilter ----------------
__global__ void k_pass1(const uint4* __restrict__ pos, const float4* __restrict__ conf,
                        const float4* __restrict__ u) {
    int img = blockIdx.y;
    int j = blockIdx.x * 256 + threadIdx.x;        // grid.x = 512 -> j in [0, 131072)
    unsigned int* h = &g_hist[img * HB];
    float pl = 0.0f; int pc = 0;

    #pragma unroll
    for (int r = 0; r < 2; r++) {
        int v = j * 2 + r;                          // float4 index, [0, 262144)
        size_t b4 = (size_t)img * (NN / 4) + v;
        uint4 p = __ldcs(&pos[b4]);                 // not re-read -> stream
        float4 c = conf[b4];                        // re-read by collect -> cache
        if (p.x) { pl += -fmaxf(logf(c.x), -100.0f); pc++; } else atomicAdd(&h[conf_bucket(c.x)], 1u);
        if (p.y) { pl += -fmaxf(logf(c.y), -100.0f); pc++; } else atomicAdd(&h[conf_bucket(c.y)], 1u);
        if (p.z) { pl += -fmaxf(logf(c.z), -100.0f); pc++; } else atomicAdd(&h[conf_bucket(c.z)], 1u);
        if (p.w) { pl += -fmaxf(logf(c.w), -100.0f); pc++; } else atomicAdd(&h[conf_bucket(c.w)], 1u);
    }

    // u prefilter with fixed conservative threshold; i<M validity deferred to select
    #pragma unroll
    for (int r = 0; r < 2; r++) {
        int v = j * 2 + r;
        if (v < U4) {
            float4 uu = __ldcs(&u[(size_t)img * U4 + v]);
            int i0 = v * 4;
            #pragma unroll
            for (int jj = 0; jj < 4; jj++) {
                float uv = (jj == 0) ? uu.x : (jj == 1) ? uu.y : (jj == 2) ? uu.z : uu.w;
                if (uv < TH0) {
                    unsigned int p = atomicAdd(&g_ucand_cnt[img], 1u);
                    if (p < UCAP) g_ucand[img * UCAP + p] = make_float2(uv, __int_as_float(i0 + jj));
                }
            }
        }
    }

    for (int o = 16; o; o >>= 1) {
        pl += __shfl_down_sync(0xffffffffu, pl, o);
        pc += __shfl_down_sync(0xffffffffu, pc, o);
    }
    __shared__ float s_pl[8]; __shared__ int s_pc[8];
    int w = threadIdx.x >> 5;
    if ((threadIdx.x & 31) == 0) { s_pl[w] = pl; s_pc[w] = pc; }
    __syncthreads();
    if (threadIdx.x == 0) {
        float tp = 0.0f; int tc = 0;
        #pragma unroll
        for (int i = 0; i < 8; i++) { tp += s_pl[i]; tc += s_pc[i]; }
        atomicAdd(&g_pos_loss[img], tp);
        atomicAdd(&g_num_pos[img], (unsigned int)tc);
    }
}

// ---------------- K3: suffix CDF per image ----------------
__global__ void k_scan() {
    int img = blockIdx.x;
    int t = threadIdx.x;                             // 1024
    const unsigned int* h = &g_hist[img * HB];
    unsigned int* S = &g_S[img * (HB + 1)];
    __shared__ unsigned int ps[1024];

    unsigned int s = 0;
    #pragma unroll 8
    for (int i = 0; i < 64; i++) s += h[t * 64 + i];
    ps[t] = s;
    __syncthreads();
    for (int off = 1; off < 1024; off <<= 1) {
        unsigned int v = (t + off < 1024) ? ps[t + off] : 0u;
        __syncthreads();
        ps[t] += v;
        __syncthreads();
    }
    unsigned int run = (t < 1023) ? ps[t + 1] : 0u;
    for (int i = 63; i >= 0; i--) {
        int b = t * 64 + i;
        run += h[b];
        S[b] = run;
    }
    if (t == 0) {
        S[HB] = 0;
        g_numneg[img] = ps[0];
        g_M[img] = (int)ps[0] - HARD;
    }
}

// ---------------- K4a: reset candidates if fallback needed ----------------
__global__ void k_ufixr() {
    int t = threadIdx.x;
    if (t < BB && g_M[t] < TRIG_M) g_ucand_cnt[t] = 0u;
}

// ---------------- K4b: fallback exact refilter (no-op normally) ----------------
__global__ void k_ufix(const float* __restrict__ u) {
    int img = blockIdx.y;
    int M = g_M[img];
    if (M >= TRIG_M) return;                         // normal case: early exit
    float th = (M <= 4096) ? 2.0f : (1280.0f / (float)M);
    int base = blockIdx.x * 256 + threadIdx.x;       // grid.x = 256 -> 65536 threads
    for (int k = 0; k < 16; k++) {
        int i = k * 65536 + base;
        if (i >= ULEN) break;
        float uv = u[(size_t)img * ULEN + i];
        if (i < M && uv < th) {
            unsigned int p = atomicAdd(&g_ucand_cnt[img], 1u);
            if (p < UCAP) g_ucand[img * UCAP + p] = make_float2(uv, __int_as_float(i));
        }
    }
}

// ---------------- K5: exact 512-smallest valid (u, idx) ----------------
__global__ void k_select() {
    int img = blockIdx.x >> 6;                        // 64 blocks/image
    int t = (blockIdx.x & 63) * 256 + threadIdx.x;    // 16384 threads >= UCAP
    unsigned int cnt = g_ucand_cnt[img];
    if (cnt > UCAP) cnt = UCAP;
    if ((unsigned int)t >= cnt) return;
    int M = g_M[img];
    const float2* base = &g_ucand[img * UCAP];
    float2 me = base[t];
    float mu = me.x; int mi = __float_as_int(me.y);
    if (mi >= M) return;                              // invalid candidate
    int r = 0;
    for (unsigned int j = 0; j < cnt; j++) {
        float2 o = base[j];
        int oi = __float_as_int(o.y);
        if (oi >= M) continue;
        r += (o.x < mu) || (o.x == mu && oi < mi);
    }
    if (r < RANDN) {
        unsigned int p = atomicAdd(&g_nranks[img], 1u);
        g_ranks[img * RANDN + p] = (unsigned int)(HARD + mi);
    }
}

// ---------------- K6: mark needed buckets ----------------
__global__ void k_mark() {
    int img = blockIdx.x;
    const unsigned int* S = &g_S[img * (HB + 1)];
    unsigned int nn = g_numneg[img];
    int HC = nn < HARD ? (int)nn : HARD;
    int nr = (int)g_nranks[img];
    int total = HC + nr;
    for (int qi = threadIdx.x; qi < total; qi += blockDim.x) {
        unsigned int q = (qi < HC) ? (unsigned int)qi : g_ranks[img * RANDN + (qi - HC)];
        int b = find_bucket(S, q);
        atomicOr(&g_bmask[img * HWRD + (b >> 5)], 1u << (b & 31));
    }
}

// ---------------- K7: exclusive prefix popcount of bitmask ----------------
__global__ void k_wpref() {
    int img = blockIdx.x;
    int t = threadIdx.x;                              // 256, 8 words each
    const unsigned int* bm = &g_bmask[img * HWRD];
    unsigned int* wp = &g_wpref[img * HWRD];
    __shared__ unsigned int ps[256];
    unsigned int loc[8];
    unsigned int s = 0;
    #pragma unroll
    for (int i = 0; i < 8; i++) { loc[i] = __popc(bm[t * 8 + i]); s += loc[i]; }
    ps[t] = s;
    __syncthreads();
    for (int off = 1; off < 256; off <<= 1) {
        unsigned int v = (t >= off) ? ps[t - off] : 0u;
        __syncthreads();
        ps[t] += v;
        __syncthreads();
    }
    unsigned int run = (t > 0) ? ps[t - 1] : 0u;
    #pragma unroll
    for (int i = 0; i < 8; i++) { wp[t * 8 + i] = run; run += loc[i]; }
}

// ---------------- K8: collect (few fat blocks -> tiny mask traffic) ----------------
__global__ void k_collect(const float4* __restrict__ conf, const unsigned int* __restrict__ pos) {
    __shared__ unsigned int mask[HWRD];               // 8KB
    __shared__ unsigned int wpref[HWRD];              // 8KB
    int img = blockIdx.y;
    for (int i = threadIdx.x; i < HWRD; i += 256) {
        mask[i] = g_bmask[img * HWRD + i];
        wpref[i] = g_wpref[img * HWRD + i];
    }
    __syncthreads();

    int base = blockIdx.x * 256 + threadIdx.x;        // grid.x = 64 -> 16384 threads
    for (int k = 0; k < 16; k++) {
        int i4 = k * 16384 + base;
        size_t b4 = (size_t)img * (NN / 4) + i4;
        float4 c = conf[b4];
        int bi = i4 * 4;
        #pragma unroll
        for (int j = 0; j < 4; j++) {
            float cv = (j == 0) ? c.x : (j == 1) ? c.y : (j == 2) ? c.z : c.w;
            int b = conf_bucket(cv);
            unsigned int mw = mask[b >> 5];
            if ((mw >> (b & 31)) & 1u) {
                if (__ldg(&pos[(size_t)img * NN + bi + j]) != 0u) continue; // rare
                int s = (int)(wpref[b >> 5] + __popc(mw & ((1u << (b & 31)) - 1u)));
                unsigned int p = atomicAdd(&g_slot_cnt[img * MAXSLOTS + s], 1u);
                if (p < SLOTCAP) g_slot_vals[(img * MAXSLOTS + s) * SLOTCAP + p] = cv;
            }
        }
    }
}

// ---------------- K9: rank queries + final reduction ----------------
__global__ void k_final(float* __restrict__ out) {
    int img = blockIdx.x;
    const unsigned int* S = &g_S[img * (HB + 1)];
    const unsigned int* bm = &g_bmask[img * HWRD];
    const unsigned int* wp = &g_wpref[img * HWRD];
    unsigned int nn = g_numneg[img];
    int HC = nn < HARD ? (int)nn : HARD;
    int nr = (int)g_nranks[img];
    int total = HC + nr;
    float hard = 0.0f, rnd = 0.0f;
    for (int qi = threadIdx.x; qi < total; qi += blockDim.x) {
        bool isHard = qi < HC;
        unsigned int q = isHard ? (unsigned int)qi : g_ranks[img * RANDN + (qi - HC)];
        int b = find_bucket(S, q);
        unsigned int j = q - S[b + 1];
        unsigned int mw = bm[b >> 5];
        int s = (int)(wp[b >> 5] + __popc(mw & ((1u << (b & 31)) - 1u)));
        unsigned int c = g_slot_cnt[img * MAXSLOTS + s];
        if (c > SLOTCAP) c = SLOTCAP;
        const float* V = &g_slot_vals[(img * MAXSLOTS + s) * SLOTCAP];
        float v = 0.5f;
        for (unsigned int k = 0; k < c; k++) {
            float x = V[k];
            unsigned int g = 0, e = 0;
            for (unsigned int l = 0; l < c; l++) { float y = V[l]; g += (y > x); e += (y == x); }
            if (g <= j && j < g + e) { v = x; break; }
        }
        float term = -fmaxf(logf(1.0f - v), -100.0f);
        if (isHard) hard += term; else rnd += term;
    }
    for (int o = 16; o; o >>= 1) {
        hard += __shfl_down_sync(0xffffffffu, hard, o);
        rnd  += __shfl_down_sync(0xffffffffu, rnd, o);
    }
    __shared__ float sh2[8], sr2[8];
    int w = threadIdx.x >> 5;
    if ((threadIdx.x & 31) == 0) { sh2[w] = hard; sr2[w] = rnd; }
    __syncthreads();
    if (threadIdx.x == 0) {
        float H = 0.0f, R = 0.0f;
        for (int i = 0; i < 8; i++) { H += sh2[i]; R += sr2[i]; }
        float P = g_pos_loss[img];
        float outv;
        if (g_M[img] > 0) {
            outv = P + H + R;
        } else {
            float sn = (float)(g_num_pos[img] + (unsigned int)HC);
            outv = (P + H) / fmaxf(sn, 1.0f);
        }
        out[img] = outv;
    }
}

extern "C" void kernel_launch(void* const* d_in, const int* in_sizes, int n_in,
                              void* d_out, int out_size) {
    const unsigned int* pos = (const unsigned int*)d_in[0];
    const float* conf = (const float*)d_in[1];
    const float* u = (const float*)d_in[2];
    float* out = (float*)d_out;
    (void)in_sizes; (void)n_in; (void)out_size;

    k_init<<<2048, 256>>>();
    {
        dim3 g(512, BB);
        k_pass1<<<g, 256>>>((const uint4*)pos, (const float4*)conf, (const float4*)u);
    }
    k_scan<<<BB, 1024>>>();
    k_ufixr<<<1, 32>>>();
    {
        dim3 g(256, BB);
        k_ufix<<<g, 256>>>(u);
    }
    k_select<<<BB * 64, 256>>>();
    k_mark<<<BB, 256>>>();
    k_wpref<<<BB, 256>>>();
    {
        dim3 g(64, BB);
        k_collect<<<g, 256>>>((const float4*)conf, pos);
    }
    k_final<<<BB, 256>>>(out);
}

// round 6
// speedup vs baseline: 2.4682x; 1.3071x over previous
#include <cuda_runtime.h>
#include <math.h>

#define BB 16
#define NN (1 << 20)
#define HB 65536
#define HWORDS (HB / 2)         // packed u16x2 words per image (32768)
#define HWRD (HB / 32)          // 2048 bitmask words per image
#define HARD 512
#define RANDN 512
#define ULEN (NN - HARD)        // 1048064
#define U4 (ULEN / 4)           // 262016
#define UCAP 16384
#define MAXSLOTS 1152
#define SLOTCAP 96
#define TH0 1.5e-3f
#define TRIG_M 853334           // fallback refilter when M < 1280/TH0
#define PARTS 8

// ---------------- scratch (static __device__, no allocs) ----------------
__device__ unsigned int g_histp[BB * HWORDS];     // packed u16x2 counters (2MB)
__device__ unsigned int g_S[BB * (HB + 1)];       // suffix CDF
__device__ unsigned int g_num_pos[BB];
__device__ float        g_pos_loss[BB];
__device__ int          g_M[BB];
__device__ unsigned int g_numneg[BB];
__device__ unsigned int g_ucand_cnt[BB];
__device__ float2       g_ucand[BB * UCAP];
__device__ unsigned int g_ranks[BB * RANDN];
__device__ unsigned int g_nranks[BB];
__device__ unsigned int g_bmask[BB * HWRD];
__device__ unsigned int g_wpref[BB * HWRD];
__device__ unsigned int g_slot_cnt[BB * MAXSLOTS];
__device__ float        g_slot_vals[BB * MAXSLOTS * SLOTCAP];

__device__ __forceinline__ int conf_bucket(float c) {
    int b = (int)(c * 65536.0f);
    b = b < 0 ? 0 : (b > HB - 1 ? HB - 1 : b);
    return b;
}

__device__ __forceinline__ int find_bucket(const unsigned int* S, unsigned int q) {
    int lo = 0, hi = HB;
    while (hi - lo > 1) {
        int mid = (lo + hi) >> 1;
        if (S[mid] > q) lo = mid; else hi = mid;
    }
    return lo;
}

// ---------------- K1: init ----------------
__global__ void k_init() {
    int idx = blockIdx.x * blockDim.x + threadIdx.x;
    int stride = gridDim.x * blockDim.x;
    for (int i = idx; i < BB * HWORDS; i += stride) g_histp[i] = 0u;
    for (int i = idx; i < BB * HWRD; i += stride) g_bmask[i] = 0u;
    for (int i = idx; i < BB * MAXSLOTS; i += stride) g_slot_cnt[i] = 0u;
    if (idx < BB) {
        g_num_pos[idx] = 0u; g_pos_loss[idx] = 0.0f;
        g_ucand_cnt[idx] = 0u; g_nranks[idx] = 0u;
    }
}

// ---------------- K2: SMEM packed-u16 histogram + pos stats + u prefilter ----------------
// grid (PARTS, BB), 1024 threads, 128KB dynamic smem
__global__ void k_pass1(const uint4* __restrict__ pos, const float4* __restrict__ conf,
                        const float4* __restrict__ u) {
    extern __shared__ unsigned int sh[];            // HWORDS words = 128KB
    int img = blockIdx.y;
    int part = blockIdx.x;
    int t = threadIdx.x;

    #pragma unroll
    for (int i = 0; i < HWORDS / 1024; i++) sh[i * 1024 + t] = 0u;
    __syncthreads();

    float pl = 0.0f; int pc = 0;
    int base4 = part * 32768;                        // float4 index base within image
    #pragma unroll 4
    for (int k = 0; k < 32; k++) {                   // 32 * 1024 * 4 = 131072 elements
        int v = base4 + k * 1024 + t;
        size_t b4 = (size_t)img * (NN / 4) + v;
        uint4 p = __ldcs(&pos[b4]);
        float4 c = conf[b4];
        if (p.x) { pl += -fmaxf(logf(c.x), -100.0f); pc++; } else { int b = conf_bucket(c.x); atomicAdd(&sh[b >> 1], 1u << ((b & 1) * 16)); }
        if (p.y) { pl += -fmaxf(logf(c.y), -100.0f); pc++; } else { int b = conf_bucket(c.y); atomicAdd(&sh[b >> 1], 1u << ((b & 1) * 16)); }
        if (p.z) { pl += -fmaxf(logf(c.z), -100.0f); pc++; } else { int b = conf_bucket(c.z); atomicAdd(&sh[b >> 1], 1u << ((b & 1) * 16)); }
        if (p.w) { pl += -fmaxf(logf(c.w), -100.0f); pc++; } else { int b = conf_bucket(c.w); atomicAdd(&sh[b >> 1], 1u << ((b & 1) * 16)); }

        // fused u prefilter on same index range
        if (v < U4) {
            float4 uu = __ldcs(&u[(size_t)img * U4 + v]);
            int i0 = v * 4;
            if (uu.x < TH0) { unsigned int q = atomicAdd(&g_ucand_cnt[img], 1u); if (q < UCAP) g_ucand[img * UCAP + q] = make_float2(uu.x, __int_as_float(i0 + 0)); }
            if (uu.y < TH0) { unsigned int q = atomicAdd(&g_ucand_cnt[img], 1u); if (q < UCAP) g_ucand[img * UCAP + q] = make_float2(uu.y, __int_as_float(i0 + 1)); }
            if (uu.z < TH0) { unsigned int q = atomicAdd(&g_ucand_cnt[img], 1u); if (q < UCAP) g_ucand[img * UCAP + q] = make_float2(uu.z, __int_as_float(i0 + 2)); }
            if (uu.w < TH0) { unsigned int q = atomicAdd(&g_ucand_cnt[img], 1u); if (q < UCAP) g_ucand[img * UCAP + q] = make_float2(uu.w, __int_as_float(i0 + 3)); }
        }
    }
    __syncthreads();

    // dump: one coalesced packed RED per nonzero word
    unsigned int* gh = &g_histp[img * HWORDS];
    #pragma unroll
    for (int i = 0; i < HWORDS / 1024; i++) {
        unsigned int w = sh[i * 1024 + t];
        if (w) atomicAdd(&gh[i * 1024 + t], w);
    }

    // pos stats
    for (int o = 16; o; o >>= 1) {
        pl += __shfl_down_sync(0xffffffffu, pl, o);
        pc += __shfl_down_sync(0xffffffffu, pc, o);
    }
    __shared__ float s_pl[32]; __shared__ int s_pc[32];
    int w = t >> 5;
    if ((t & 31) == 0) { s_pl[w] = pl; s_pc[w] = pc; }
    __syncthreads();
    if (t == 0) {
        float tp = 0.0f; int tc = 0;
        #pragma unroll
        for (int i = 0; i < 32; i++) { tp += s_pl[i]; tc += s_pc[i]; }
        atomicAdd(&g_pos_loss[img], tp);
        atomicAdd(&g_num_pos[img], (unsigned int)tc);
    }
}

// ---------------- K3: suffix CDF per image (unpack packed hist) ----------------
__global__ void k_scan() {
    int img = blockIdx.x;
    int t = threadIdx.x;                             // 1024
    const unsigned int* hp = &g_histp[img * HWORDS];
    unsigned int* S = &g_S[img * (HB + 1)];
    __shared__ unsigned int ps[1024];

    unsigned int cnt[64];                            // 64 bins = 32 words per thread
    unsigned int s = 0;
    #pragma unroll
    for (int i = 0; i < 32; i++) {
        unsigned int w = hp[t * 32 + i];
        cnt[i * 2] = w & 0xffffu;
        cnt[i * 2 + 1] = w >> 16;
        s += cnt[i * 2] + cnt[i * 2 + 1];
    }
    ps[t] = s;
    __syncthreads();
    for (int off = 1; off < 1024; off <<= 1) {
        unsigned int v = (t + off < 1024) ? ps[t + off] : 0u;
        __syncthreads();
        ps[t] += v;
        __syncthreads();
    }
    unsigned int run = (t < 1023) ? ps[t + 1] : 0u;
    #pragma unroll
    for (int i = 63; i >= 0; i--) {
        run += cnt[i];
        S[t * 64 + i] = run;
    }
    if (t == 0) {
        S[HB] = 0;
        g_numneg[img] = ps[0];
        g_M[img] = (int)ps[0] - HARD;
    }
}

// ---------------- K4a: reset candidates if fallback needed ----------------
__global__ void k_ufixr() {
    int t = threadIdx.x;
    if (t < BB && g_M[t] < TRIG_M) g_ucand_cnt[t] = 0u;
}

// ---------------- K4b: fallback exact refilter (no-op normally) ----------------
__global__ void k_ufix(const float* __restrict__ u) {
    int img = blockIdx.y;
    int M = g_M[img];
    if (M >= TRIG_M) return;
    float th = (M <= 4096) ? 2.0f : (1280.0f / (float)M);
    int base = blockIdx.x * 256 + threadIdx.x;
    for (int k = 0; k < 16; k++) {
        int i = k * 65536 + base;
        if (i >= ULEN) break;
        float uv = u[(size_t)img * ULEN + i];
        if (i < M && uv < th) {
            unsigned int p = atomicAdd(&g_ucand_cnt[img], 1u);
            if (p < UCAP) g_ucand[img * UCAP + p] = make_float2(uv, __int_as_float(i));
        }
    }
}

// ---------------- K5: exact 512-smallest valid (u, idx) ----------------
__global__ void k_select() {
    int img = blockIdx.x >> 6;
    int t = (blockIdx.x & 63) * 256 + threadIdx.x;
    unsigned int cnt = g_ucand_cnt[img];
    if (cnt > UCAP) cnt = UCAP;
    if ((unsigned int)t >= cnt) return;
    int M = g_M[img];
    const float2* base = &g_ucand[img * UCAP];
    float2 me = base[t];
    float mu = me.x; int mi = __float_as_int(me.y);
    if (mi >= M) return;
    int r = 0;
    for (unsigned int j = 0; j < cnt; j++) {
        float2 o = base[j];
        int oi = __float_as_int(o.y);
        if (oi >= M) continue;
        r += (o.x < mu) || (o.x == mu && oi < mi);
    }
    if (r < RANDN) {
        unsigned int p = atomicAdd(&g_nranks[img], 1u);
        g_ranks[img * RANDN + p] = (unsigned int)(HARD + mi);
    }
}

// ---------------- K6: mark needed buckets ----------------
__global__ void k_mark() {
    int img = blockIdx.x;
    const unsigned int* S = &g_S[img * (HB + 1)];
    unsigned int nn = g_numneg[img];
    int HC = nn < HARD ? (int)nn : HARD;
    int nr = (int)g_nranks[img];
    int total = HC + nr;
    for (int qi = threadIdx.x; qi < total; qi += blockDim.x) {
        unsigned int q = (qi < HC) ? (unsigned int)qi : g_ranks[img * RANDN + (qi - HC)];
        int b = find_bucket(S, q);
        atomicOr(&g_bmask[img * HWRD + (b >> 5)], 1u << (b & 31));
    }
}

// ---------------- K7: exclusive prefix popcount of bitmask ----------------
__global__ void k_wpref() {
    int img = blockIdx.x;
    int t = threadIdx.x;                              // 256, 8 words each
    const unsigned int* bm = &g_bmask[img * HWRD];
    unsigned int* wp = &g_wpref[img * HWRD];
    __shared__ unsigned int ps[256];
    unsigned int loc[8];
    unsigned int s = 0;
    #pragma unroll
    for (int i = 0; i < 8; i++) { loc[i] = __popc(bm[t * 8 + i]); s += loc[i]; }
    ps[t] = s;
    __syncthreads();
    for (int off = 1; off < 256; off <<= 1) {
        unsigned int v = (t >= off) ? ps[t - off] : 0u;
        __syncthreads();
        ps[t] += v;
        __syncthreads();
    }
    unsigned int run = (t > 0) ? ps[t - 1] : 0u;
    #pragma unroll
    for (int i = 0; i < 8; i++) { wp[t * 8 + i] = run; run += loc[i]; }
}

// ---------------- K8: collect ----------------
__global__ void k_collect(const float4* __restrict__ conf, const unsigned int* __restrict__ pos) {
    __shared__ unsigned int mask[HWRD];
    __shared__ unsigned int wpref[HWRD];
    int img = blockIdx.y;
    for (int i = threadIdx.x; i < HWRD; i += 256) {
        mask[i] = g_bmask[img * HWRD + i];
        wpref[i] = g_wpref[img * HWRD + i];
    }
    __syncthreads();

    int base = blockIdx.x * 256 + threadIdx.x;        // grid.x = 64
    for (int k = 0; k < 16; k++) {
        int i4 = k * 16384 + base;
        size_t b4 = (size_t)img * (NN / 4) + i4;
        float4 c = conf[b4];
        int bi = i4 * 4;
        #pragma unroll
        for (int j = 0; j < 4; j++) {
            float cv = (j == 0) ? c.x : (j == 1) ? c.y : (j == 2) ? c.z : c.w;
            int b = conf_bucket(cv);
            unsigned int mw = mask[b >> 5];
            if ((mw >> (b & 31)) & 1u) {
                if (__ldg(&pos[(size_t)img * NN + bi + j]) != 0u) continue;
                int s = (int)(wpref[b >> 5] + __popc(mw & ((1u << (b & 31)) - 1u)));
                unsigned int p = atomicAdd(&g_slot_cnt[img * MAXSLOTS + s], 1u);
                if (p < SLOTCAP) g_slot_vals[(img * MAXSLOTS + s) * SLOTCAP + p] = cv;
            }
        }
    }
}

// ---------------- K9: rank queries + final reduction ----------------
__global__ void k_final(float* __restrict__ out) {
    int img = blockIdx.x;
    const unsigned int* S = &g_S[img * (HB + 1)];
    const unsigned int* bm = &g_bmask[img * HWRD];
    const unsigned int* wp = &g_wpref[img * HWRD];
    unsigned int nn = g_numneg[img];
    int HC = nn < HARD ? (int)nn : HARD;
    int nr = (int)g_nranks[img];
    int total = HC + nr;
    float hard = 0.0f, rnd = 0.0f;
    for (int qi = threadIdx.x; qi < total; qi += blockDim.x) {
        bool isHard = qi < HC;
        unsigned int q = isHard ? (unsigned int)qi : g_ranks[img * RANDN + (qi - HC)];
        int b = find_bucket(S, q);
        unsigned int j = q - S[b + 1];
        unsigned int mw = bm[b >> 5];
        int s = (int)(wp[b >> 5] + __popc(mw & ((1u << (b & 31)) - 1u)));
        unsigned int c = g_slot_cnt[img * MAXSLOTS + s];
        if (c > SLOTCAP) c = SLOTCAP;
        const float* V = &g_slot_vals[(img * MAXSLOTS + s) * SLOTCAP];
        float v = 0.5f;
        for (unsigned int k = 0; k < c; k++) {
            float x = V[k];
            unsigned int g = 0, e = 0;
            for (unsigned int l = 0; l < c; l++) { float y = V[l]; g += (y > x); e += (y == x); }
            if (g <= j && j < g + e) { v = x; break; }
        }
        float term = -fmaxf(logf(1.0f - v), -100.0f);
        if (isHard) hard += term; else rnd += term;
    }
    for (int o = 16; o; o >>= 1) {
        hard += __shfl_down_sync(0xffffffffu, hard, o);
        rnd  += __shfl_down_sync(0xffffffffu, rnd, o);
    }
    __shared__ float sh2[8], sr2[8];
    int w = threadIdx.x >> 5;
    if ((threadIdx.x & 31) == 0) { sh2[w] = hard; sr2[w] = rnd; }
    __syncthreads();
    if (threadIdx.x == 0) {
        float H = 0.0f, R = 0.0f;
        for (int i = 0; i < 8; i++) { H += sh2[i]; R += sr2[i]; }
        float P = g_pos_loss[img];
        float outv;
        if (g_M[img] > 0) {
            outv = P + H + R;
        } else {
            float sn = (float)(g_num_pos[img] + (unsigned int)HC);
            outv = (P + H) / fmaxf(sn, 1.0f);
        }
        out[img] = outv;
    }
}

extern "C" void kernel_launch(void* const* d_in, const int* in_sizes, int n_in,
                              void* d_out, int out_size) {
    const unsigned int* pos = (const unsigned int*)d_in[0];
    const float* conf = (const float*)d_in[1];
    const float* u = (const float*)d_in[2];
    float* out = (float*)d_out;
    (void)in_sizes; (void)n_in; (void)out_size;

    cudaFuncSetAttribute(k_pass1, cudaFuncAttributeMaxDynamicSharedMemorySize, HWORDS * 4);

    k_init<<<2048, 256>>>();
    {
        dim3 g(PARTS, BB);
        k_pass1<<<g, 1024, HWORDS * 4>>>((const uint4*)pos, (const float4*)conf, (const float4*)u);
    }
    k_scan<<<BB, 1024>>>();
    k_ufixr<<<1, 32>>>();
    {
        dim3 g(256, BB);
        k_ufix<<<g, 256>>>(u);
    }
    k_select<<<BB * 64, 256>>>();
    k_mark<<<BB, 256>>>();
    k_wpref<<<BB, 256>>>();
    {
        dim3 g(64, BB);
        k_collect<<<g, 256>>>((const float4*)conf, pos);
    }
    k_final<<<BB, 256>>>(out);
}

// round 8
// speedup vs baseline: 3.0829x; 1.2491x over previous
#include <cuda_runtime.h>
#include <math.h>

#define BB 16
#define NN (1 << 20)
#define HB 65536
#define HWRD (HB / 32)          // 2048 bitmask words per image
#define HARD 512
#define RANDN 512
#define ULEN (NN - HARD)        // 1048064
#define U4 (ULEN / 4)           // 262016
#define UCAP 16384
#define MAXSLOTS 1152
#define SLOTCAP 96
#define TH0 1.5e-3f
#define TRIG_M 853334           // fallback refilter when M < 1280/TH0
#define PARTS 16
#define P4 16384                // float4 per part (65536 elems)
#define PW 16384                // u8x4 words per part (65536 bins / 4)
#define SCNT_STRIDE 66          // u16 smem stride (bank-conflict-free)

// ---------------- scratch (static __device__, zero at load; re-zeroed by k_final) ----------------
__device__ unsigned int g_parts[BB * PARTS * PW]; // 16MB u8x4, fully overwritten each run
__device__ unsigned int g_S[BB * (HB + 1)];       // suffix CDF, fully overwritten
__device__ unsigned int g_num_pos[BB];            // atomic -> zeroed by k_final
__device__ float        g_pos_loss[BB];           // atomic -> zeroed by k_final
__device__ int          g_M[BB];                  // overwritten
__device__ unsigned int g_numneg[BB];             // overwritten
__device__ unsigned int g_ucand_cnt[BB];          // atomic -> zeroed by k_final
__device__ float2       g_ucand[BB * UCAP];       // governed by cnt
__device__ unsigned int g_ranks[BB * RANDN];      // governed by nranks
__device__ unsigned int g_nranks[BB];             // overwritten by k_post
__device__ unsigned int g_bmask[BB * HWRD];       // fully overwritten by k_post
__device__ unsigned int g_wpref[BB * HWRD];       // fully overwritten by k_post
__device__ unsigned int g_slot_cnt[BB * MAXSLOTS];// atomic -> zeroed by k_final
__device__ float        g_slot_vals[BB * MAXSLOTS * SLOTCAP]; // governed by cnt

__device__ __forceinline__ int conf_bucket(float c) {
    int b = (int)(c * 65536.0f);
    b = b < 0 ? 0 : (b > HB - 1 ? HB - 1 : b);
    return b;
}

__device__ __forceinline__ int find_bucket(const unsigned int* S, unsigned int q) {
    int lo = 0, hi = HB;
    while (hi - lo > 1) {
        int mid = (lo + hi) >> 1;
        if (S[mid] > q) lo = mid; else hi = mid;
    }
    return lo;
}

// ---------------- K2: SMEM u8 histogram + pos stats + u prefilter ----------------
// grid (PARTS, BB), 512 threads, 64KB dynamic smem
__global__ void __launch_bounds__(512) k_pass1(
        const uint4* __restrict__ pos, const float4* __restrict__ conf,
        const float4* __restrict__ u) {
    extern __shared__ unsigned int sh[];            // PW words (u8x4) = 64KB
    int img = blockIdx.y;
    int part = blockIdx.x;
    int t = threadIdx.x;

    #pragma unroll
    for (int i = 0; i < PW / 512; i++) sh[i * 512 + t] = 0u;
    __syncthreads();

    float pl = 0.0f; int pc = 0;
    int base4 = part * P4;
    #pragma unroll 4
    for (int k = 0; k < P4 / 512; k++) {            // 32 iterations
        int v = base4 + k * 512 + t;
        size_t b4 = (size_t)img * (NN / 4) + v;
        uint4 p = __ldcs(&pos[b4]);
        float4 c = conf[b4];
        if (p.x) { pl += -fmaxf(logf(c.x), -100.0f); pc++; } else { int b = conf_bucket(c.x); atomicAdd(&sh[b >> 2], 1u << ((b & 3) * 8)); }
        if (p.y) { pl += -fmaxf(logf(c.y), -100.0f); pc++; } else { int b = conf_bucket(c.y); atomicAdd(&sh[b >> 2], 1u << ((b & 3) * 8)); }
        if (p.z) { pl += -fmaxf(logf(c.z), -100.0f); pc++; } else { int b = conf_bucket(c.z); atomicAdd(&sh[b >> 2], 1u << ((b & 3) * 8)); }
        if (p.w) { pl += -fmaxf(logf(c.w), -100.0f); pc++; } else { int b = conf_bucket(c.w); atomicAdd(&sh[b >> 2], 1u << ((b & 3) * 8)); }

        if (v < U4) {
            float4 uu = __ldcs(&u[(size_t)img * U4 + v]);
            int i0 = v * 4;
            if (uu.x < TH0) { unsigned int q = atomicAdd(&g_ucand_cnt[img], 1u); if (q < UCAP) g_ucand[img * UCAP + q] = make_float2(uu.x, __int_as_float(i0 + 0)); }
            if (uu.y < TH0) { unsigned int q = atomicAdd(&g_ucand_cnt[img], 1u); if (q < UCAP) g_ucand[img * UCAP + q] = make_float2(uu.y, __int_as_float(i0 + 1)); }
            if (uu.z < TH0) { unsigned int q = atomicAdd(&g_ucand_cnt[img], 1u); if (q < UCAP) g_ucand[img * UCAP + q] = make_float2(uu.z, __int_as_float(i0 + 2)); }
            if (uu.w < TH0) { unsigned int q = atomicAdd(&g_ucand_cnt[img], 1u); if (q < UCAP) g_ucand[img * UCAP + q] = make_float2(uu.w, __int_as_float(i0 + 3)); }
        }
    }
    __syncthreads();

    // dump: plain coalesced stores (no atomics); g_parts fully overwritten
    unsigned int* dst = &g_parts[(unsigned int)(img * PARTS + part) * PW];
    #pragma unroll
    for (int i = 0; i < PW / 512; i++) dst[i * 512 + t] = sh[i * 512 + t];

    // pos stats
    for (int o = 16; o; o >>= 1) {
        pl += __shfl_down_sync(0xffffffffu, pl, o);
        pc += __shfl_down_sync(0xffffffffu, pc, o);
    }
    __shared__ float s_pl[16]; __shared__ int s_pc[16];
    int w = t >> 5;
    if ((t & 31) == 0) { s_pl[w] = pl; s_pc[w] = pc; }
    __syncthreads();
    if (t == 0) {
        float tp = 0.0f; int tc = 0;
        #pragma unroll
        for (int i = 0; i < 16; i++) { tp += s_pl[i]; tc += s_pc[i]; }
        atomicAdd(&g_pos_loss[img], tp);
        atomicAdd(&g_num_pos[img], (unsigned int)tc);
    }
}

// ---------------- K3: sum parts + suffix CDF per image ----------------
// grid BB, 1024 threads, dynamic smem = 1024*SCNT_STRIDE*2 bytes
__global__ void __launch_bounds__(1024) k_scan() {
    extern __shared__ unsigned short scnt[];        // [t*SCNT_STRIDE + k], k<64
    __shared__ unsigned int ps[1024];
    int img = blockIdx.x;
    int t = threadIdx.x;
    unsigned int* S = &g_S[img * (HB + 1)];

    unsigned int s = 0;
    for (int i = 0; i < 4; i++) {                   // uint4 groups: bins t*64 + i*16 + [0,16)
        unsigned int b16[16];
        #pragma unroll
        for (int k = 0; k < 16; k++) b16[k] = 0;
        for (int p = 0; p < PARTS; p++) {
            const uint4* src = (const uint4*)&g_parts[(unsigned int)(img * PARTS + p) * PW];
            uint4 w4 = src[t * 4 + i];
            b16[0] += w4.x & 0xffu; b16[1] += (w4.x >> 8) & 0xffu; b16[2] += (w4.x >> 16) & 0xffu; b16[3] += w4.x >> 24;
            b16[4] += w4.y & 0xffu; b16[5] += (w4.y >> 8) & 0xffu; b16[6] += (w4.y >> 16) & 0xffu; b16[7] += w4.y >> 24;
            b16[8] += w4.z & 0xffu; b16[9] += (w4.z >> 8) & 0xffu; b16[10] += (w4.z >> 16) & 0xffu; b16[11] += w4.z >> 24;
            b16[12] += w4.w & 0xffu; b16[13] += (w4.w >> 8) & 0xffu; b16[14] += (w4.w >> 16) & 0xffu; b16[15] += w4.w >> 24;
        }
        #pragma unroll
        for (int k = 0; k < 16; k++) {
            scnt[t * SCNT_STRIDE + i * 16 + k] = (unsigned short)b16[k];
            s += b16[k];
        }
    }
    ps[t] = s;
    __syncthreads();
    for (int off = 1; off < 1024; off <<= 1) {      // inclusive suffix scan
        unsigned int v = (t + off < 1024) ? ps[t + off] : 0u;
        __syncthreads();
        ps[t] += v;
        __syncthreads();
    }
    unsigned int run = (t < 1023) ? ps[t + 1] : 0u;
    for (int q = 63; q >= 0; q--) {
        run += scnt[t * SCNT_STRIDE + q];
        S[t * 64 + q] = run;
    }
    if (t == 0) {
        S[HB] = 0;
        unsigned int nn = ps[0];
        g_numneg[img] = nn;
        int M = (int)nn - HARD;
        g_M[img] = M;
        if (M < TRIG_M) g_ucand_cnt[img] = 0u;      // trigger fallback refilter
    }
}

// ---------------- K4: fallback exact refilter (no-op normally) ----------------
__global__ void __launch_bounds__(256) k_ufix(const float* __restrict__ u) {
    int img = blockIdx.y;
    int M = g_M[img];
    if (M >= TRIG_M) return;
    float th = (M <= 4096) ? 2.0f : (1280.0f / (float)M);
    int base = blockIdx.x * 256 + threadIdx.x;      // grid.x = 64 -> 16384 threads
    for (int k = 0; k < 64; k++) {
        int i = k * 16384 + base;
        if (i >= ULEN) break;
        float uv = u[(size_t)img * ULEN + i];
        if (i < M && uv < th) {
            unsigned int p = atomicAdd(&g_ucand_cnt[img], 1u);
            if (p < UCAP) g_ucand[img * UCAP + p] = make_float2(uv, __int_as_float(i));
        }
    }
}

// ---------------- K5: fused select + mark + wpref (grid BB, 1024 thr, 128KB dyn) ----------------
__global__ void __launch_bounds__(1024) k_post() {
    extern __shared__ float2 cs[];                  // UCAP float2 = 128KB
    __shared__ unsigned int h256[256];
    __shared__ unsigned int bidx[1024];
    __shared__ unsigned int bm_s[HWRD];             // 8KB
    __shared__ unsigned int ps[1024];
    __shared__ unsigned int s_nr, s_bcnt, s_kb, s_needB;

    int img = blockIdx.x;
    int t = threadIdx.x;
    unsigned int cnt = g_ucand_cnt[img];
    if (cnt > UCAP) cnt = UCAP;
    int M = g_M[img];
    float thr = (M < TRIG_M) ? ((M <= 4096) ? 2.0f : 1280.0f / (float)M) : TH0;
    float binscale = 256.0f / thr;

    if (t < 256) h256[t] = 0u;
    if (t == 0) { s_nr = 0u; s_bcnt = 0u; }
    __syncthreads();

    for (unsigned int i = t; i < cnt; i += 1024) {
        float2 c = g_ucand[img * UCAP + i];
        cs[i] = c;
        int mi = __float_as_int(c.y);
        if (mi < M) {
            int b = (int)(c.x * binscale); if (b > 255) b = 255;
            atomicAdd(&h256[b], 1u);
        }
    }
    __syncthreads();

    if (t == 0) {
        unsigned int tot = 0;
        for (int b = 0; b < 256; b++) tot += h256[b];
        int kb = 256; unsigned int need = 0;
        if (tot > RANDN) {
            unsigned int cum = 0;
            for (int b = 0; b < 256; b++) {
                if (cum + h256[b] >= RANDN) { kb = b; need = RANDN - cum; break; }
                cum += h256[b];
            }
        }
        s_kb = (unsigned int)kb; s_needB = need;
    }
    __syncthreads();
    int kb = (int)s_kb; unsigned int needB = s_needB;

    for (unsigned int i = t; i < cnt; i += 1024) {
        float2 c = cs[i];
        int mi = __float_as_int(c.y);
        if (mi >= M) continue;
        int b = (int)(c.x * binscale); if (b > 255) b = 255;
        if (b < kb) {
            unsigned int p = atomicAdd(&s_nr, 1u);
            g_ranks[img * RANDN + p] = (unsigned int)(HARD + mi);
        } else if (b == kb) {
            unsigned int p = atomicAdd(&s_bcnt, 1u);
            if (p < 1024) bidx[p] = i;
        }
    }
    __syncthreads();

    unsigned int bc = s_bcnt; if (bc > 1024) bc = 1024;
    if ((unsigned int)t < bc) {
        float2 me = cs[bidx[t]];
        float mu = me.x; int mi = __float_as_int(me.y);
        unsigned int r = 0;
        for (unsigned int j = 0; j < bc; j++) {
            float2 o = cs[bidx[j]];
            int oi = __float_as_int(o.y);
            r += (o.x < mu) || (o.x == mu && oi < mi);
        }
        if (r < needB) {
            unsigned int p = atomicAdd(&s_nr, 1u);
            g_ranks[img * RANDN + p] = (unsigned int)(HARD + mi);
        }
    }
    __syncthreads();
    unsigned int nr = s_nr;
    if (t == 0) g_nranks[img] = nr;

    // mark into smem bitmask
    for (int i = t; i < HWRD; i += 1024) bm_s[i] = 0u;
    __syncthreads();
    const unsigned int* S = &g_S[img * (HB + 1)];
    unsigned int nn = g_numneg[img];
    int HC = nn < HARD ? (int)nn : HARD;
    int total = HC + (int)nr;
    for (int qi = t; qi < total; qi += 1024) {
        unsigned int q = (qi < HC) ? (unsigned int)qi : g_ranks[img * RANDN + (qi - HC)];
        int b = find_bucket(S, q);
        atomicOr(&bm_s[b >> 5], 1u << (b & 31));
    }
    __syncthreads();

    // wpref: exclusive prefix popcount over 2048 words (2 per thread)
    unsigned int w0 = bm_s[t * 2], w1 = bm_s[t * 2 + 1];
    unsigned int l0 = __popc(w0), l1 = __popc(w1);
    ps[t] = l0 + l1;
    __syncthreads();
    for (int off = 1; off < 1024; off <<= 1) {
        unsigned int v = (t >= off) ? ps[t - off] : 0u;
        __syncthreads();
        ps[t] += v;
        __syncthreads();
    }
    unsigned int run = (t > 0) ? ps[t - 1] : 0u;
    g_wpref[img * HWRD + t * 2] = run;
    g_wpref[img * HWRD + t * 2 + 1] = run + l0;
    g_bmask[img * HWRD + t * 2] = w0;
    g_bmask[img * HWRD + t * 2 + 1] = w1;
}

// ---------------- K8: collect ----------------
__global__ void __launch_bounds__(256) k_collect(
        const float4* __restrict__ conf, const unsigned int* __restrict__ pos) {
    __shared__ unsigned int mask[HWRD];
    __shared__ unsigned int wpref[HWRD];
    int img = blockIdx.y;
    for (int i = threadIdx.x; i < HWRD; i += 256) {
        mask[i] = g_bmask[img * HWRD + i];
        wpref[i] = g_wpref[img * HWRD + i];
    }
    __syncthreads();

    int base = blockIdx.x * 256 + threadIdx.x;      // grid.x = 64
    for (int k = 0; k < 16; k++) {
        int i4 = k * 16384 + base;
        size_t b4 = (size_t)img * (NN / 4) + i4;
        float4 c = conf[b4];
        int bi = i4 * 4;
        #pragma unroll
        for (int j = 0; j < 4; j++) {
            float cv = (j == 0) ? c.x : (j == 1) ? c.y : (j == 2) ? c.z : c.w;
            int b = conf_bucket(cv);
            unsigned int mw = mask[b >> 5];
            if ((mw >> (b & 31)) & 1u) {
                if (__ldg(&pos[(size_t)img * NN + bi + j]) != 0u) continue;
                int s = (int)(wpref[b >> 5] + __popc(mw & ((1u << (b & 31)) - 1u)));
                unsigned int p = atomicAdd(&g_slot_cnt[img * MAXSLOTS + s], 1u);
                if (p < SLOTCAP) g_slot_vals[(img * MAXSLOTS + s) * SLOTCAP + p] = cv;
            }
        }
    }
}

// ---------------- K9: rank queries + final reduction + scratch re-zero ----------------
__global__ void __launch_bounds__(256) k_final(float* __restrict__ out) {
    int img = blockIdx.x;
    const unsigned int* S = &g_S[img * (HB + 1)];
    const unsigned int* bm = &g_bmask[img * HWRD];
    const unsigned int* wp = &g_wpref[img * HWRD];
    unsigned int nn = g_numneg[img];
    int HC = nn < HARD ? (int)nn : HARD;
    int nr = (int)g_nranks[img];
    int total = HC + nr;
    float hard = 0.0f, rnd = 0.0f;
    for (int qi = threadIdx.x; qi < total; qi += blockDim.x) {
        bool isHard = qi < HC;
        unsigned int q = isHard ? (unsigned int)qi : g_ranks[img * RANDN + (qi - HC)];
        int b = find_bucket(S, q);
        unsigned int j = q - S[b + 1];
        unsigned int mw = bm[b >> 5];
        int s = (int)(wp[b >> 5] + __popc(mw & ((1u << (b & 31)) - 1u)));
        unsigned int c = g_slot_cnt[img * MAXSLOTS + s];
        if (c > SLOTCAP) c = SLOTCAP;
        const float* V = &g_slot_vals[(img * MAXSLOTS + s) * SLOTCAP];
        float v = 0.5f;
        for (unsigned int k = 0; k < c; k++) {
            float x = V[k];
            unsigned int g = 0, e = 0;
            for (unsigned int l = 0; l < c; l++) { float y = V[l]; g += (y > x); e += (y == x); }
            if (g <= j && j < g + e) { v = x; break; }
        }
        float term = -fmaxf(logf(1.0f - v), -100.0f);
        if (isHard) hard += term; else rnd += term;
    }
    for (int o = 16; o; o >>= 1) {
        hard += __shfl_down_sync(0xffffffffu, hard, o);
        rnd  += __shfl_down_sync(0xffffffffu, rnd, o);
    }
    __shared__ float sh2[8], sr2[8];
    int w = threadIdx.x >> 5;
    if ((threadIdx.x & 31) == 0) { sh2[w] = hard; sr2[w] = rnd; }
    __syncthreads();
    if (threadIdx.x == 0) {
        float H = 0.0f, R = 0.0f;
        for (int i = 0; i < 8; i++) { H += sh2[i]; R += sr2[i]; }
        float P = g_pos_loss[img];
        float outv;
        if (g_M[img] > 0) {
            outv = P + H + R;
        } else {
            float sn = (float)(g_num_pos[img] + (unsigned int)HC);
            outv = (P + H) / fmaxf(sn, 1.0f);
        }
        out[img] = outv;
    }
    __syncthreads();
    // re-zero atomic-accumulated scratch for next run
    for (int i = threadIdx.x; i < MAXSLOTS; i += blockDim.x) g_slot_cnt[img * MAXSLOTS + i] = 0u;
    if (threadIdx.x == 0) {
        g_ucand_cnt[img] = 0u;
        g_pos_loss[img] = 0.0f;
        g_num_pos[img] = 0u;
    }
}

extern "C" void kernel_launch(void* const* d_in, const int* in_sizes, int n_in,
                              void* d_out, int out_size) {
    const unsigned int* pos = (const unsigned int*)d_in[0];
    const float* conf = (const float*)d_in[1];
    const float* u = (const float*)d_in[2];
    float* out = (float*)d_out;
    (void)in_sizes; (void)n_in; (void)out_size;

    cudaFuncSetAttribute(k_pass1, cudaFuncAttributeMaxDynamicSharedMemorySize, PW * 4);
    cudaFuncSetAttribute(k_scan, cudaFuncAttributeMaxDynamicSharedMemorySize, 1024 * SCNT_STRIDE * 2);
    cudaFuncSetAttribute(k_post, cudaFuncAttributeMaxDynamicSharedMemorySize, UCAP * 8);

    {
        dim3 g(PARTS, BB);
        k_pass1<<<g, 512, PW * 4>>>((const uint4*)pos, (const float4*)conf, (const float4*)u);
    }
    k_scan<<<BB, 1024, 1024 * SCNT_STRIDE * 2>>>();
    {
        dim3 g(64, BB);
        k_ufix<<<g, 256>>>(u);
    }
    k_post<<<BB, 1024, UCAP * 8>>>();
    {
        dim3 g(64, BB);
        k_collect<<<g, 256>>>((const float4*)conf, pos);
    }
    k_final<<<BB, 256>>>(out);
}